// round 3
// baseline (speedup 1.0000x reference)
#include <cuda_runtime.h>
#include <cuda_bf16.h>
#include <cstdint>

// Problem constants (fixed by dataset)
#define DFEAT 512
#define NOUT  64
#define MAXN  100032   // N_NODES rounded up to 64

// Scratch for projected features h = x @ W   (25.6 MB, static device global)
__device__ float g_h[(size_t)MAXN * NOUT];

// ---------------------------------------------------------------------------
// Kernel 1: zero the output accumulator (d_out is poisoned by the harness)
// ---------------------------------------------------------------------------
__global__ void zero_kernel(float4* __restrict__ p, int n4) {
    int i = blockIdx.x * blockDim.x + threadIdx.x;
    if (i < n4) p[i] = make_float4(0.f, 0.f, 0.f, 0.f);
}

// ---------------------------------------------------------------------------
// Kernel 2: h = x @ W   [N,512] x [512,64] -> [N,64], fp32 with packed FFMA2
// Block: 256 threads, tile 64 rows x 64 cols, BK=16.
// Thread (tc=tid&15, tr=tid>>4) computes rows tr*4..+3, cols tc*4..+3.
// Accumulators pack ROW PAIRS in f32x2: accA[c] = (h[r0][c], h[r1][c]),
// accB[c] = (h[r2][c], h[r3][c]).  xs is stored k-major so the a-operand
// (x[kk][r0..r3]) is one LDS.128 giving two ready-packed 64-bit halves.
// ---------------------------------------------------------------------------
__global__ void __launch_bounds__(256) gemm_kernel(const float* __restrict__ x,
                                                   const float* __restrict__ W,
                                                   int n_rows)
{
    __shared__ __align__(16) float xs[16][64];   // [kk][row]
    __shared__ __align__(16) float ws[16][64];   // [kk][col]

    const int tid  = threadIdx.x;
    const int row0 = blockIdx.x * 64;

    // loader mapping
    const int lrow = tid >> 2;          // 0..63
    const int lkq  = (tid & 3) * 4;     // 0,4,8,12
    const int wk   = tid >> 4;          // 0..15
    const int wc   = (tid & 15) * 4;    // 0..60

    const int  grow = row0 + lrow;
    const bool rok  = grow < n_rows;
    const float* xptr = x + (size_t)(rok ? grow : 0) * DFEAT + lkq;
    const float* wptr = W + (size_t)wk * NOUT + wc;

    // compute mapping
    const int cb = (tid & 15) * 4;      // col base
    const int rb = (tid >> 4) * 4;      // row base

    unsigned long long accA0 = 0, accA1 = 0, accA2 = 0, accA3 = 0;
    unsigned long long accB0 = 0, accB1 = 0, accB2 = 0, accB3 = 0;

    // prefetch first tile
    float4 xv = rok ? *(const float4*)xptr : make_float4(0.f, 0.f, 0.f, 0.f);
    float4 wv = *(const float4*)wptr;

    for (int kt = 0; kt < DFEAT / 16; ++kt) {
        // store prefetched tile (x transposed to k-major)
        xs[lkq + 0][lrow] = xv.x;
        xs[lkq + 1][lrow] = xv.y;
        xs[lkq + 2][lrow] = xv.z;
        xs[lkq + 3][lrow] = xv.w;
        *(float4*)&ws[wk][wc] = wv;
        __syncthreads();

        if (kt < DFEAT / 16 - 1) {
            xv = rok ? *(const float4*)(xptr + (kt + 1) * 16)
                     : make_float4(0.f, 0.f, 0.f, 0.f);
            wv = *(const float4*)(wptr + (size_t)(kt + 1) * 16 * NOUT);
        }

#pragma unroll
        for (int kk = 0; kk < 16; ++kk) {
            ulonglong2 a = *(const ulonglong2*)&xs[kk][rb];  // (x[r0],x[r1]),(x[r2],x[r3])
            float4 wf = *(const float4*)&ws[kk][cb];
            unsigned long long b0, b1, b2, b3;
            asm("mov.b64 %0,{%1,%1};" : "=l"(b0) : "f"(wf.x));
            asm("mov.b64 %0,{%1,%1};" : "=l"(b1) : "f"(wf.y));
            asm("mov.b64 %0,{%1,%1};" : "=l"(b2) : "f"(wf.z));
            asm("mov.b64 %0,{%1,%1};" : "=l"(b3) : "f"(wf.w));
            asm("fma.rn.f32x2 %0,%1,%2,%0;" : "+l"(accA0) : "l"(a.x), "l"(b0));
            asm("fma.rn.f32x2 %0,%1,%2,%0;" : "+l"(accA1) : "l"(a.x), "l"(b1));
            asm("fma.rn.f32x2 %0,%1,%2,%0;" : "+l"(accA2) : "l"(a.x), "l"(b2));
            asm("fma.rn.f32x2 %0,%1,%2,%0;" : "+l"(accA3) : "l"(a.x), "l"(b3));
            asm("fma.rn.f32x2 %0,%1,%2,%0;" : "+l"(accB0) : "l"(a.y), "l"(b0));
            asm("fma.rn.f32x2 %0,%1,%2,%0;" : "+l"(accB1) : "l"(a.y), "l"(b1));
            asm("fma.rn.f32x2 %0,%1,%2,%0;" : "+l"(accB2) : "l"(a.y), "l"(b2));
            asm("fma.rn.f32x2 %0,%1,%2,%0;" : "+l"(accB3) : "l"(a.y), "l"(b3));
        }
        __syncthreads();
    }

    // unpack & store: accA holds rows (rb, rb+1), accB rows (rb+2, rb+3)
    float2 a0 = *reinterpret_cast<float2*>(&accA0);
    float2 a1 = *reinterpret_cast<float2*>(&accA1);
    float2 a2 = *reinterpret_cast<float2*>(&accA2);
    float2 a3 = *reinterpret_cast<float2*>(&accA3);
    float2 c0 = *reinterpret_cast<float2*>(&accB0);
    float2 c1 = *reinterpret_cast<float2*>(&accB1);
    float2 c2 = *reinterpret_cast<float2*>(&accB2);
    float2 c3 = *reinterpret_cast<float2*>(&accB3);

    float4 rows[4];
    rows[0] = make_float4(a0.x, a1.x, a2.x, a3.x);
    rows[1] = make_float4(a0.y, a1.y, a2.y, a3.y);
    rows[2] = make_float4(c0.x, c1.x, c2.x, c3.x);
    rows[3] = make_float4(c0.y, c1.y, c2.y, c3.y);

#pragma unroll
    for (int r = 0; r < 4; ++r) {
        int gr = row0 + rb + r;
        if (gr < n_rows)
            *(float4*)&g_h[(size_t)gr * NOUT + cb] = rows[r];
    }
}

// ---------------------------------------------------------------------------
// Kernel 3: scatter  out[dst] += h[src] * w    via vectorized RED.128
// 16 lanes per edge, each lane owns 4 consecutive channels.
// ---------------------------------------------------------------------------
__global__ void __launch_bounds__(256) scatter_kernel(const int*   __restrict__ esrc,
                                                      const int*   __restrict__ edst,
                                                      const float* __restrict__ ew,
                                                      float*       __restrict__ out,
                                                      int n_edges)
{
    int t = blockIdx.x * blockDim.x + threadIdx.x;
    int e = t >> 4;
    if (e >= n_edges) return;
    int lane = t & 15;

    int   s = __ldg(&esrc[e]);
    int   d = __ldg(&edst[e]);
    float w = __ldg(&ew[e]);

    float4 v = *(const float4*)&g_h[(size_t)s * NOUT + lane * 4];
    v.x *= w; v.y *= w; v.z *= w; v.w *= w;

    float* p = &out[(size_t)d * NOUT + lane * 4];
    asm volatile("red.global.add.v4.f32 [%0], {%1, %2, %3, %4};"
                 :: "l"(p), "f"(v.x), "f"(v.y), "f"(v.z), "f"(v.w)
                 : "memory");
}

// ---------------------------------------------------------------------------
// Kernel 4: row softmax over 64 channels, in place. One warp per row.
// ---------------------------------------------------------------------------
__global__ void __launch_bounds__(256) softmax_kernel(float* __restrict__ out, int n_rows)
{
    int gw   = (blockIdx.x * blockDim.x + threadIdx.x) >> 5;
    int lane = threadIdx.x & 31;
    if (gw >= n_rows) return;

    float2 v = *(float2*)&out[(size_t)gw * NOUT + lane * 2];

    float m = fmaxf(v.x, v.y);
#pragma unroll
    for (int o = 16; o > 0; o >>= 1)
        m = fmaxf(m, __shfl_xor_sync(0xffffffffu, m, o));

    float e0 = __expf(v.x - m);
    float e1 = __expf(v.y - m);
    float s = e0 + e1;
#pragma unroll
    for (int o = 16; o > 0; o >>= 1)
        s += __shfl_xor_sync(0xffffffffu, s, o);

    float inv = 1.0f / s;
    float2 r = make_float2(e0 * inv, e1 * inv);
    *(float2*)&out[(size_t)gw * NOUT + lane * 2] = r;
}

// ---------------------------------------------------------------------------
// Launch.  Input order per metadata: x, edge_src, edge_dst, edge_w, W.
// ---------------------------------------------------------------------------
extern "C" void kernel_launch(void* const* d_in, const int* in_sizes, int n_in,
                              void* d_out, int out_size)
{
    const float* x    = (const float*)d_in[0];
    const int*   esrc = (const int*)  d_in[1];
    const int*   edst = (const int*)  d_in[2];
    const float* ew   = (const float*)d_in[3];
    const float* W    = (const float*)d_in[4];
    float*       out  = (float*)d_out;

    const int n_nodes = in_sizes[0] / DFEAT;
    const int n_edges = in_sizes[1];

    // 1) zero accumulator (d_out is poisoned)
    {
        int n4 = n_nodes * NOUT / 4;
        zero_kernel<<<(n4 + 255) / 256, 256>>>((float4*)out, n4);
    }
    // 2) h = x @ W
    {
        int blocks = (n_nodes + 63) / 64;
        gemm_kernel<<<blocks, 256>>>(x, W, n_nodes);
    }
    // 3) scatter-add messages
    {
        long long threads = (long long)n_edges * 16;
        int blocks = (int)((threads + 255) / 256);
        scatter_kernel<<<blocks, 256>>>(esrc, edst, ew, out, n_edges);
    }
    // 4) softmax rows
    {
        long long threads = (long long)n_nodes * 32;
        int blocks = (int)((threads + 255) / 256);
        softmax_kernel<<<blocks, 256>>>(out, n_nodes);
    }
}